// round 1
// baseline (speedup 1.0000x reference)
#include <cuda_runtime.h>

#define HID 256
#define TILE_E 32
#define EMAX 131072
#define NDEPTH 3
#define BN_EPS 1e-5f

// Scratch (static device arrays: allocation-free)
__device__ int g_cnt[4];
__device__ int g_bucket[4 * EMAX];

__global__ void reset_kernel() {
    if (threadIdx.x < 4) g_cnt[threadIdx.x] = 0;
}

// Partition edges into 4 branch buckets (warp-aggregated atomics).
__global__ void bucket_kernel(const int* __restrict__ edx_ij,
                              const int* __restrict__ edx_jk,
                              const int* __restrict__ nei_ptr, int E) {
    int e = blockIdx.x * blockDim.x + threadIdx.x;
    int lane = threadIdx.x & 31;
    bool valid = (e < E);
    int nei = nei_ptr[0];
    int br = 0;
    if (valid) {
        int mij = (edx_ij[e] < nei) ? 1 : 0;
        int mjk = (edx_jk[e] < nei) ? 1 : 0;
        br = ((mij ^ 1) << 1) | (mjk ^ 1);   // 0:ij&jk 1:ij&~jk 2:~ij&jk 3:~ij&~jk
    }
    #pragma unroll
    for (int b = 0; b < 4; b++) {
        unsigned m = __ballot_sync(0xffffffffu, valid && br == b);
        if (!m) continue;
        int leader = __ffs(m) - 1;
        int base = 0;
        if (lane == leader) base = atomicAdd(&g_cnt[b], __popc(m));
        base = __shfl_sync(0xffffffffu, base, leader);
        if (valid && br == b) {
            int rank = __popc(m & ((1u << lane) - 1u));
            g_bucket[b * EMAX + base + rank] = e;
        }
    }
}

// GEMM inner: acc[e] += sum_k Xs[e][k] * W[k*HID + c], K = HID, with weight prefetch.
__device__ __forceinline__ void gemm_accum(float acc[TILE_E],
                                           const float (*Xs)[HID],
                                           const float* __restrict__ W, int c) {
    float w0 = W[0 * HID + c], w1 = W[1 * HID + c];
    float w2 = W[2 * HID + c], w3 = W[3 * HID + c];
    for (int k = 0; k < HID; k += 4) {
        float cw0 = w0, cw1 = w1, cw2 = w2, cw3 = w3;
        if (k + 4 < HID) {
            w0 = W[(k + 4) * HID + c];
            w1 = W[(k + 5) * HID + c];
            w2 = W[(k + 6) * HID + c];
            w3 = W[(k + 7) * HID + c];
        }
        #pragma unroll
        for (int e = 0; e < TILE_E; e++) {
            float4 x = *reinterpret_cast<const float4*>(&Xs[e][k]);
            acc[e] = fmaf(x.x, cw0, acc[e]);
            acc[e] = fmaf(x.y, cw1, acc[e]);
            acc[e] = fmaf(x.z, cw2, acc[e]);
            acc[e] = fmaf(x.w, cw3, acc[e]);
        }
    }
}

__global__ __launch_bounds__(256, 2)
void mlp_kernel(const float* __restrict__ nf, const float* __restrict__ geo,
                const int* __restrict__ eidx,
                const float* __restrict__ att,
                const float* __restrict__ W0, const float* __restrict__ b0,
                const float* __restrict__ Wh, const float* __restrict__ bh,
                const float* __restrict__ gamma, const float* __restrict__ beta,
                const float* __restrict__ rmean, const float* __restrict__ rvar,
                float* __restrict__ out, int E, int G) {
    extern __shared__ unsigned char smem_raw[];
    float (*Xs)[HID] = reinterpret_cast<float (*)[HID]>(smem_raw);
    float (*Hs)[HID] = reinterpret_cast<float (*)[HID]>(smem_raw + TILE_E * HID * 4);
    int* s_edge = reinterpret_cast<int*>(smem_raw + 2 * TILE_E * HID * 4);
    int* s_i = s_edge + TILE_E;
    int* s_j = s_i + TILE_E;
    int* s_k = s_j + TILE_E;

    const int br = blockIdx.y;
    const int cnt = g_cnt[br];
    const int base = blockIdx.x * TILE_E;
    if (base >= cnt) return;
    const int ne = min(TILE_E, cnt - base);
    const int tid = threadIdx.x;
    const int c = tid;  // output channel owned by this thread

    if (tid < TILE_E) {
        int t = min(tid, ne - 1);           // pad tile with duplicate of last edge
        int e = g_bucket[br * EMAX + base + t];
        s_edge[tid] = e;
        s_i[tid] = eidx[e];
        s_j[tid] = eidx[E + e];
        s_k[tid] = eidx[2 * E + e];
    }
    __syncthreads();

    float acc[TILE_E];
    #pragma unroll
    for (int e = 0; e < TILE_E; e++) acc[e] = 0.f;

    const float* W0b = W0 + (size_t)br * (3 * HID + 0 + 13) * HID;
    // NOTE: d_in row count for W0 is 3*HID + G; G is runtime (13). Recompute:
    const int DIN = 3 * HID + G;
    W0b = W0 + (size_t)br * DIN * HID;

    // ---- layer 0: three node-feature segments of K=256 each ----
    for (int seg = 0; seg < 3; seg++) {
        const int* srcidx = (seg == 0) ? s_i : (seg == 1) ? s_j : s_k;
        for (int idx = tid; idx < TILE_E * HID; idx += 256) {
            int e = idx >> 8, kk = idx & (HID - 1);
            Xs[e][kk] = nf[(size_t)srcidx[e] * HID + kk];
        }
        __syncthreads();
        gemm_accum(acc, Xs, W0b + (size_t)seg * HID * HID, c);
        __syncthreads();
    }
    // ---- layer 0: geo segment (K = G) ----
    for (int idx = tid; idx < TILE_E * G; idx += 256) {
        int e = idx / G, kk = idx - e * G;
        Xs[e][kk] = geo[(size_t)s_edge[e] * G + kk];
    }
    __syncthreads();
    {
        const float* Wg = W0b + (size_t)(3 * HID) * HID;
        for (int k = 0; k < G; k++) {
            float w = Wg[k * HID + c];
            #pragma unroll
            for (int e = 0; e < TILE_E; e++) acc[e] = fmaf(Xs[e][k], w, acc[e]);
        }
    }
    __syncthreads();

    // BN(layer0) + bias + ReLU -> Hs
    {
        const float* g = gamma + ((size_t)br * (NDEPTH + 1) + 0) * HID;
        const float* bt = beta + ((size_t)br * (NDEPTH + 1) + 0) * HID;
        const float* m = rmean + ((size_t)br * (NDEPTH + 1) + 0) * HID;
        const float* v = rvar + ((size_t)br * (NDEPTH + 1) + 0) * HID;
        const float* bi = b0 + (size_t)br * HID;
        float sc = g[c] * rsqrtf(v[c] + BN_EPS);
        float sh = (bi[c] - m[c]) * sc + bt[c];
        #pragma unroll
        for (int e = 0; e < TILE_E; e++) {
            Hs[e][c] = fmaxf(fmaf(acc[e], sc, sh), 0.f);
            acc[e] = 0.f;
        }
    }
    __syncthreads();

    // ---- hidden layers ----
    for (int l = 0; l < NDEPTH; l++) {
        const float* W = Wh + ((size_t)(br * NDEPTH + l) * HID) * HID;
        gemm_accum(acc, Hs, W, c);
        __syncthreads();

        const float* g = gamma + ((size_t)br * (NDEPTH + 1) + l + 1) * HID;
        const float* bt = beta + ((size_t)br * (NDEPTH + 1) + l + 1) * HID;
        const float* m = rmean + ((size_t)br * (NDEPTH + 1) + l + 1) * HID;
        const float* v = rvar + ((size_t)br * (NDEPTH + 1) + l + 1) * HID;
        const float* bi = bh + ((size_t)(br * NDEPTH + l)) * HID;
        float sc = g[c] * rsqrtf(v[c] + BN_EPS);
        float sh = (bi[c] - m[c]) * sc + bt[c];

        if (l < NDEPTH - 1) {
            #pragma unroll
            for (int e = 0; e < TILE_E; e++) {
                Hs[e][c] = fmaxf(fmaf(acc[e], sc, sh), 0.f);
                acc[e] = 0.f;
            }
            __syncthreads();
        } else {
            // final layer: relu >= 0, so leaky_relu is identity; scale by att and scatter
            float a = att[br];
            #pragma unroll
            for (int e = 0; e < TILE_E; e++) {
                float val = fmaxf(fmaf(acc[e], sc, sh), 0.f) * a;
                if (e < ne) atomicAdd(&out[(size_t)s_i[e] * HID + c], val);
            }
        }
    }
}

extern "C" void kernel_launch(void* const* d_in, const int* in_sizes, int n_in,
                              void* d_out, int out_size) {
    const float* nf     = (const float*)d_in[0];
    const float* geo    = (const float*)d_in[1];
    const int*   eidx   = (const int*)d_in[2];
    const int*   edx_ij = (const int*)d_in[3];
    const int*   edx_jk = (const int*)d_in[4];
    const float* att    = (const float*)d_in[5];
    const float* W0     = (const float*)d_in[6];
    const float* b0     = (const float*)d_in[7];
    const float* Wh     = (const float*)d_in[8];
    const float* bh     = (const float*)d_in[9];
    const float* gamma  = (const float*)d_in[10];
    const float* beta   = (const float*)d_in[11];
    const float* rmean  = (const float*)d_in[12];
    const float* rvar   = (const float*)d_in[13];
    const int*   nei    = (const int*)d_in[14];

    int E = in_sizes[3];            // edx_ij length
    int G = in_sizes[1] / E;        // geo feature width (13)
    float* out = (float*)d_out;

    cudaMemsetAsync(out, 0, (size_t)out_size * sizeof(float), 0);
    reset_kernel<<<1, 32>>>();
    bucket_kernel<<<(E + 255) / 256, 256>>>(edx_ij, edx_jk, nei, E);

    const int smem_bytes = 2 * TILE_E * HID * 4 + 4 * TILE_E * 4;
    cudaFuncSetAttribute(mlp_kernel, cudaFuncAttributeMaxDynamicSharedMemorySize,
                         smem_bytes);
    dim3 grid((E + TILE_E - 1) / TILE_E, 4);
    mlp_kernel<<<grid, 256, smem_bytes>>>(nf, geo, eidx, att, W0, b0, Wh, bh,
                                          gamma, beta, rmean, rvar, out, E, G);
}

// round 4
// speedup vs baseline: 4.9056x; 4.9056x over previous
#include <cuda_runtime.h>
#include <cstdint>

#define EMAX 131072
#define HID 256
#define TILE 128
#define KF0 784            // 781 padded to 49 chunks of 16
#define KC 16
#define BN_EPS 1e-5f

// smem strides (floats) — chosen for conflict-free mma fragment access
#define ASTR 20
#define BSTR 264
#define HSTR 260

// smem float offsets
#define OFF_BIAS 512                   // after 4*128 ints of edge indices
#define OFF_A    768                   // 2 * 128*20  = 5120
#define OFF_B    (OFF_A + 5120)        // 2 * 16*264  = 8448
#define OFF_H    (OFF_B + 8448)        // 128*260    = 33280
#define SMEM_BYTES ((OFF_H + 33280) * 4)

static __device__ int   g_cnt[4];
static __device__ int   g_bucket[4 * EMAX];
static __device__ float g_w0t[4 * KF0 * HID];      // [br][kf][n], BN-folded, tf32-rounded
static __device__ float g_wht[4 * 3 * HID * HID];  // [br][l][k][n], BN-folded, tf32-rounded
static __device__ float g_biasf[4 * 4 * HID];      // [br][layer][n]

__device__ __forceinline__ float to_tf32(float x) {
    float r; asm("cvt.rn.tf32.f32 %0, %1;" : "=f"(r) : "f"(x)); return r;
}

__device__ __forceinline__ void mma8(float* d, const float* a, const float* b) {
    asm volatile(
        "mma.sync.aligned.m16n8k8.row.col.f32.tf32.tf32.f32 "
        "{%0,%1,%2,%3}, {%4,%5,%6,%7}, {%8,%9}, {%0,%1,%2,%3};"
        : "+f"(d[0]), "+f"(d[1]), "+f"(d[2]), "+f"(d[3])
        : "r"(__float_as_uint(a[0])), "r"(__float_as_uint(a[1])),
          "r"(__float_as_uint(a[2])), "r"(__float_as_uint(a[3])),
          "r"(__float_as_uint(b[0])), "r"(__float_as_uint(b[1])));
}

__device__ __forceinline__ void red2(float* p, float x, float y) {
    asm volatile("red.global.add.v2.f32 [%0], {%1,%2};" :: "l"(p), "f"(x), "f"(y) : "memory");
}

// ---------------- prep kernels ----------------
__global__ void reset_kernel() { if (threadIdx.x < 4) g_cnt[threadIdx.x] = 0; }

__global__ void bucket_kernel(const int* __restrict__ edx_ij, const int* __restrict__ edx_jk,
                              const int* __restrict__ nei_ptr, int E) {
    int e = blockIdx.x * blockDim.x + threadIdx.x;
    int lane = threadIdx.x & 31;
    bool valid = (e < E);
    int nei = nei_ptr[0];
    int br = 0;
    if (valid) {
        int mij = (edx_ij[e] < nei) ? 1 : 0;
        int mjk = (edx_jk[e] < nei) ? 1 : 0;
        br = ((mij ^ 1) << 1) | (mjk ^ 1);
    }
    #pragma unroll
    for (int b = 0; b < 4; b++) {
        unsigned m = __ballot_sync(0xffffffffu, valid && br == b);
        if (!m) continue;
        int leader = __ffs(m) - 1;
        int base = 0;
        if (lane == leader) base = atomicAdd(&g_cnt[b], __popc(m));
        base = __shfl_sync(0xffffffffu, base, leader);
        if (valid && br == b) {
            int rank = __popc(m & ((1u << lane) - 1u));
            g_bucket[b * EMAX + base + rank] = e;
        }
    }
}

// g_w0t[br][kf][n] = tf32(W0[br][kf][n] * sc0[br][n]); zero for kf >= din
__global__ void prep_w0(const float* __restrict__ W0, const float* __restrict__ gamma,
                        const float* __restrict__ rvar, int din) {
    int idx = blockIdx.x * blockDim.x + threadIdx.x;
    if (idx >= 4 * KF0 * HID) return;
    int n = idx % HID, kf = (idx / HID) % KF0, br = idx / (HID * KF0);
    float sc = gamma[(br * 4 + 0) * HID + n] * rsqrtf(rvar[(br * 4 + 0) * HID + n] + BN_EPS);
    float v = 0.f;
    if (kf < din) v = W0[((size_t)br * din + kf) * HID + n] * sc;
    g_w0t[idx] = to_tf32(v);
}

// g_wht[br][l][k][n] = tf32(Wh[br][l][k][n] * sc[br][l+1][n])
__global__ void prep_wh(const float* __restrict__ Wh, const float* __restrict__ gamma,
                        const float* __restrict__ rvar) {
    int idx = blockIdx.x * blockDim.x + threadIdx.x;
    if (idx >= 4 * 3 * HID * HID) return;
    int n = idx % HID, k = (idx / HID) % HID;
    int l = (idx / (HID * HID)) % 3, br = idx / (3 * HID * HID);
    float sc = gamma[(br * 4 + l + 1) * HID + n] * rsqrtf(rvar[(br * 4 + l + 1) * HID + n] + BN_EPS);
    g_wht[idx] = to_tf32(Wh[idx] * sc);
}

__global__ void prep_bias(const float* __restrict__ b0, const float* __restrict__ bh,
                          const float* __restrict__ gamma, const float* __restrict__ beta,
                          const float* __restrict__ rmean, const float* __restrict__ rvar) {
    int idx = blockIdx.x * blockDim.x + threadIdx.x;
    if (idx >= 4 * 4 * HID) return;
    int n = idx % HID, l = (idx / HID) % 4, br = idx / (4 * HID);
    int gi = (br * 4 + l) * HID + n;
    float sc = gamma[gi] * rsqrtf(rvar[gi] + BN_EPS);
    float b = (l == 0) ? b0[br * HID + n] : bh[((size_t)(br * 3) + (l - 1)) * HID + n];
    g_biasf[idx] = (b - rmean[gi]) * sc + beta[gi];
}

// ---------------- main fused MLP kernel (mma.sync tf32) ----------------
__global__ __launch_bounds__(256, 1)
void mlp_mma_kernel(const float* __restrict__ nf, const float* __restrict__ geo,
                    const int* __restrict__ eidx, const float* __restrict__ att,
                    float* __restrict__ out, int E, int G) {
    extern __shared__ float sm[];
    int* s_i = (int*)sm;
    int* s_j = s_i + 128;
    int* s_k = s_j + 128;
    int* s_e = s_k + 128;
    float* bias_s = sm + OFF_BIAS;
    float* Asm = sm + OFF_A;
    float* Bsm = sm + OFF_B;
    float* Hsm = sm + OFF_H;

    const int br = blockIdx.y;
    const int cnt = g_cnt[br];
    const int tstart = blockIdx.x * TILE;
    if (tstart >= cnt) return;
    const int ne = min(TILE, cnt - tstart);
    const int tid = threadIdx.x;
    const int warp = tid >> 5, lane = tid & 31;
    const int t4 = lane >> 2, tm4 = lane & 3;
    const int rbase = (warp & 1) * 64;        // M block of this warp
    const int nbase = (warp >> 1) * 64;       // N block of this warp

    if (tid < 128) {
        int t = min(tid, ne - 1);             // pad tile with last valid edge
        int e = g_bucket[br * EMAX + tstart + t];
        s_e[tid] = e;
        s_i[tid] = eidx[e];
        s_j[tid] = eidx[E + e];
        s_k[tid] = eidx[2 * E + e];
    }
    __syncthreads();

    float acc[4][8][4];

    for (int l = 0; l < 4; l++) {
        const int nch = (l == 0) ? (KF0 / KC) : (HID / KC);
        const float* Wsrc = (l == 0) ? (g_w0t + (size_t)br * KF0 * HID)
                                     : (g_wht + ((size_t)(br * 3) + (l - 1)) * HID * HID);

        #pragma unroll
        for (int m = 0; m < 4; m++)
            #pragma unroll
            for (int n = 0; n < 8; n++)
                #pragma unroll
                for (int q = 0; q < 4; q++) acc[m][n][q] = 0.f;

        // ---- stage chunk 0 + bias for this layer ----
        bias_s[tid] = g_biasf[((size_t)(br * 4) + l) * HID + tid];
        {   // B chunk 0
            const float* src = Wsrc;
            #pragma unroll
            for (int p = 0; p < 4; p++) {
                int idx = p * 256 + tid;
                int row = idx >> 6, q = idx & 63;
                float4 v = *(const float4*)(src + row * HID + q * 4);
                *(float4*)(Bsm + row * BSTR + q * 4) = v;
            }
        }
        if (l == 0) {   // A chunk 0 (features 0..15 of node i)
            #pragma unroll
            for (int p = 0; p < 2; p++) {
                int idx = p * 256 + tid;
                int row = idx >> 2, q = idx & 3;
                float4 v = *(const float4*)(nf + (size_t)s_i[row] * HID + q * 4);
                v.x = to_tf32(v.x); v.y = to_tf32(v.y);
                v.z = to_tf32(v.z); v.w = to_tf32(v.w);
                *(float4*)(Asm + row * ASTR + q * 4) = v;
            }
        }
        __syncthreads();

        for (int c = 0; c < nch; c++) {
            const int buf = c & 1;
            // ---- stage chunk c+1 into the other buffer ----
            if (c + 1 < nch) {
                const int nb = buf ^ 1;
                {
                    const float* src = Wsrc + (size_t)(c + 1) * KC * HID;
                    float* dst = Bsm + nb * (KC * BSTR);
                    #pragma unroll
                    for (int p = 0; p < 4; p++) {
                        int idx = p * 256 + tid;
                        int row = idx >> 6, q = idx & 63;
                        float4 v = *(const float4*)(src + row * HID + q * 4);
                        *(float4*)(dst + row * BSTR + q * 4) = v;
                    }
                }
                if (l == 0) {
                    const int cn = c + 1;
                    float* dst = Asm + nb * (128 * ASTR);
                    if (cn < 48) {
                        const int* sidx = (cn < 16) ? s_i : (cn < 32) ? s_j : s_k;
                        const int f0 = (cn & 15) * 16;
                        #pragma unroll
                        for (int p = 0; p < 2; p++) {
                            int idx = p * 256 + tid;
                            int row = idx >> 2, q = idx & 3;
                            float4 v = *(const float4*)(nf + (size_t)sidx[row] * HID + f0 + q * 4);
                            v.x = to_tf32(v.x); v.y = to_tf32(v.y);
                            v.z = to_tf32(v.z); v.w = to_tf32(v.w);
                            *(float4*)(dst + row * ASTR + q * 4) = v;
                        }
                    } else {
                        // geo chunk: feats 768..783 -> geo[0..G-1], zero pad
                        #pragma unroll
                        for (int p = 0; p < 8; p++) {
                            int idx = p * 256 + tid;
                            int row = idx >> 4, fi = idx & 15;
                            float v = (fi < G) ? to_tf32(geo[(size_t)s_e[row] * G + fi]) : 0.f;
                            dst[row * ASTR + fi] = v;
                        }
                    }
                }
            }

            // ---- compute chunk c: 2 k-steps of 8 ----
            const float* Abase;
            int astr, koff;
            if (l == 0) { Abase = Asm + buf * (128 * ASTR); astr = ASTR; koff = 0; }
            else        { Abase = Hsm;                      astr = HSTR; koff = c * KC; }
            const float* Bbase = Bsm + buf * (KC * BSTR);

            #pragma unroll
            for (int s = 0; s < 2; s++) {
                float a[4][4];
                float b[8][2];
                #pragma unroll
                for (int m = 0; m < 4; m++) {
                    const float* ap = Abase + (rbase + m * 16 + t4) * astr + koff + s * 8 + tm4;
                    a[m][0] = ap[0];
                    a[m][1] = ap[8 * astr];
                    a[m][2] = ap[4];
                    a[m][3] = ap[8 * astr + 4];
                }
                #pragma unroll
                for (int n = 0; n < 8; n++) {
                    const float* bp = Bbase + (s * 8 + tm4) * BSTR + nbase + n * 8 + t4;
                    b[n][0] = bp[0];
                    b[n][1] = bp[4 * BSTR];
                }
                #pragma unroll
                for (int m = 0; m < 4; m++)
                    #pragma unroll
                    for (int n = 0; n < 8; n++)
                        mma8(acc[m][n], a[m], b[n]);
            }
            __syncthreads();
        }

        // ---- epilogue ----
        if (l < 3) {
            // bias + ReLU + tf32-round -> Hsm (next layer's A)
            #pragma unroll
            for (int m = 0; m < 4; m++) {
                const int r0 = rbase + m * 16 + t4;
                #pragma unroll
                for (int n = 0; n < 8; n++) {
                    const int c0 = nbase + n * 8 + 2 * tm4;
                    const float b0v = bias_s[c0], b1v = bias_s[c0 + 1];
                    float2 v0, v1;
                    v0.x = to_tf32(fmaxf(acc[m][n][0] + b0v, 0.f));
                    v0.y = to_tf32(fmaxf(acc[m][n][1] + b1v, 0.f));
                    v1.x = to_tf32(fmaxf(acc[m][n][2] + b0v, 0.f));
                    v1.y = to_tf32(fmaxf(acc[m][n][3] + b1v, 0.f));
                    *(float2*)(Hsm + r0 * HSTR + c0) = v0;
                    *(float2*)(Hsm + (r0 + 8) * HSTR + c0) = v1;
                }
            }
            __syncthreads();
        } else {
            // bias + ReLU (leaky_relu is identity on >=0), * att, scatter to out[i]
            const float attv = __ldg(att + br);
            #pragma unroll
            for (int m = 0; m < 4; m++) {
                const int r0 = rbase + m * 16 + t4;
                const int r1 = r0 + 8;
                float* o0 = (r0 < ne) ? (out + (size_t)s_i[r0] * HID) : 0;
                float* o1 = (r1 < ne) ? (out + (size_t)s_i[r1] * HID) : 0;
                #pragma unroll
                for (int n = 0; n < 8; n++) {
                    const int c0 = nbase + n * 8 + 2 * tm4;
                    const float b0v = bias_s[c0], b1v = bias_s[c0 + 1];
                    if (o0) red2(o0 + c0, fmaxf(acc[m][n][0] + b0v, 0.f) * attv,
                                          fmaxf(acc[m][n][1] + b1v, 0.f) * attv);
                    if (o1) red2(o1 + c0, fmaxf(acc[m][n][2] + b0v, 0.f) * attv,
                                          fmaxf(acc[m][n][3] + b1v, 0.f) * attv);
                }
            }
        }
    }
}

// ---------------- launch ----------------
extern "C" void kernel_launch(void* const* d_in, const int* in_sizes, int n_in,
                              void* d_out, int out_size) {
    const float* nf     = (const float*)d_in[0];
    const float* geo    = (const float*)d_in[1];
    const int*   eidx   = (const int*)d_in[2];
    const int*   edx_ij = (const int*)d_in[3];
    const int*   edx_jk = (const int*)d_in[4];
    const float* att    = (const float*)d_in[5];
    const float* W0     = (const float*)d_in[6];
    const float* b0     = (const float*)d_in[7];
    const float* Wh     = (const float*)d_in[8];
    const float* bh     = (const float*)d_in[9];
    const float* gamma  = (const float*)d_in[10];
    const float* beta   = (const float*)d_in[11];
    const float* rmean  = (const float*)d_in[12];
    const float* rvar   = (const float*)d_in[13];
    const int*   nei    = (const int*)d_in[14];

    int E = in_sizes[3];
    int G = in_sizes[1] / E;
    int din = 3 * HID + G;
    float* out = (float*)d_out;

    cudaMemsetAsync(out, 0, (size_t)out_size * sizeof(float), 0);
    reset_kernel<<<1, 32>>>();
    bucket_kernel<<<(E + 255) / 256, 256>>>(edx_ij, edx_jk, nei, E);

    prep_w0<<<(4 * KF0 * HID + 255) / 256, 256>>>(W0, gamma, rvar, din);
    prep_wh<<<(4 * 3 * HID * HID + 255) / 256, 256>>>(Wh, gamma, rvar);
    prep_bias<<<(4 * 4 * HID + 255) / 256, 256>>>(b0, bh, gamma, beta, rmean, rvar);

    cudaFuncSetAttribute(mlp_mma_kernel, cudaFuncAttributeMaxDynamicSharedMemorySize,
                         SMEM_BYTES);
    dim3 grid((E + TILE - 1) / TILE, 4);
    mlp_mma_kernel<<<grid, 256, SMEM_BYTES>>>(nf, geo, eidx, att, out, E, G);
}

// round 5
// speedup vs baseline: 7.1334x; 1.4541x over previous
#include <cuda_runtime.h>
#include <cstdint>

#define EMAX 131072
#define HID 256
#define TILE 128
#define KF0 784            // 781 padded to 49 chunks of 16
#define KC 16
#define BN_EPS 1e-5f

// smem strides (floats) — conflict-free mma fragment access
#define ASTR 20
#define BSTR 264
#define HSTR 260

// smem float offsets
#define OFF_BIAS 512
#define OFF_A    768                   // 2 * 128*20  = 5120
#define OFF_B    (OFF_A + 5120)        // 2 * 16*264  = 8448
#define OFF_H    (OFF_B + 8448)        // 128*260    = 33280
#define SMEM_BYTES ((OFF_H + 33280) * 4)

static __device__ int   g_cnt[4];
static __device__ int   g_bucket[4 * EMAX];
static __device__ float g_w0t[4 * KF0 * HID];      // [br][kf][n], BN-folded, tf32-rn
static __device__ float g_wht[4 * 3 * HID * HID];  // [br][l][k][n], BN-folded, tf32-rn
static __device__ float g_biasf[4 * 4 * HID];      // [br][layer][n]

__device__ __forceinline__ float to_tf32(float x) {
    float r; asm("cvt.rn.tf32.f32 %0, %1;" : "=f"(r) : "f"(x)); return r;
}
__device__ __forceinline__ uint32_t smem_u32(const void* p) {
    uint32_t a;
    asm("{ .reg .u64 t; cvta.to.shared.u64 t, %1; cvt.u32.u64 %0, t; }" : "=r"(a) : "l"(p));
    return a;
}
__device__ __forceinline__ void cpa16(uint32_t dst, const void* src) {
    asm volatile("cp.async.cg.shared.global [%0], [%1], 16;" :: "r"(dst), "l"(src));
}
#define CPA_COMMIT() asm volatile("cp.async.commit_group;" ::: "memory")
#define CPA_WAIT0()  asm volatile("cp.async.wait_group 0;" ::: "memory")

__device__ __forceinline__ void mma8(float* d, const float* a, const float* b) {
    asm volatile(
        "mma.sync.aligned.m16n8k8.row.col.f32.tf32.tf32.f32 "
        "{%0,%1,%2,%3}, {%4,%5,%6,%7}, {%8,%9}, {%0,%1,%2,%3};"
        : "+f"(d[0]), "+f"(d[1]), "+f"(d[2]), "+f"(d[3])
        : "r"(__float_as_uint(a[0])), "r"(__float_as_uint(a[1])),
          "r"(__float_as_uint(a[2])), "r"(__float_as_uint(a[3])),
          "r"(__float_as_uint(b[0])), "r"(__float_as_uint(b[1])));
}

__device__ __forceinline__ void red2(float* p, float x, float y) {
    asm volatile("red.global.add.v2.f32 [%0], {%1,%2};" :: "l"(p), "f"(x), "f"(y) : "memory");
}

// ---------------- prep kernels ----------------
__global__ void reset_kernel() { if (threadIdx.x < 4) g_cnt[threadIdx.x] = 0; }

__global__ void bucket_kernel(const int* __restrict__ edx_ij, const int* __restrict__ edx_jk,
                              const int* __restrict__ nei_ptr, int E) {
    int e = blockIdx.x * blockDim.x + threadIdx.x;
    int lane = threadIdx.x & 31;
    bool valid = (e < E);
    int nei = nei_ptr[0];
    int br = 0;
    if (valid) {
        int mij = (edx_ij[e] < nei) ? 1 : 0;
        int mjk = (edx_jk[e] < nei) ? 1 : 0;
        br = ((mij ^ 1) << 1) | (mjk ^ 1);
    }
    #pragma unroll
    for (int b = 0; b < 4; b++) {
        unsigned m = __ballot_sync(0xffffffffu, valid && br == b);
        if (!m) continue;
        int leader = __ffs(m) - 1;
        int base = 0;
        if (lane == leader) base = atomicAdd(&g_cnt[b], __popc(m));
        base = __shfl_sync(0xffffffffu, base, leader);
        if (valid && br == b) {
            int rank = __popc(m & ((1u << lane) - 1u));
            g_bucket[b * EMAX + base + rank] = e;
        }
    }
}

// One fused prep kernel: W0 fold, Wh fold, bias fold.
#define N_W0 (4 * KF0 * HID)
#define N_WH (4 * 3 * HID * HID)
#define N_BI (4 * 4 * HID)
__global__ void prep_all(const float* __restrict__ W0, const float* __restrict__ Wh,
                         const float* __restrict__ b0, const float* __restrict__ bh,
                         const float* __restrict__ gamma, const float* __restrict__ beta,
                         const float* __restrict__ rmean, const float* __restrict__ rvar,
                         int din) {
    int idx = blockIdx.x * blockDim.x + threadIdx.x;
    if (idx < N_W0) {
        int n = idx % HID, kf = (idx / HID) % KF0, br = idx / (HID * KF0);
        float sc = gamma[(br * 4 + 0) * HID + n] * rsqrtf(rvar[(br * 4 + 0) * HID + n] + BN_EPS);
        float v = 0.f;
        if (kf < din) v = W0[((size_t)br * din + kf) * HID + n] * sc;
        g_w0t[idx] = to_tf32(v);
        return;
    }
    int j = idx - N_W0;
    if (j < N_WH) {
        int n = j % HID;
        int l = (j / (HID * HID)) % 3, br = j / (3 * HID * HID);
        float sc = gamma[(br * 4 + l + 1) * HID + n] *
                   rsqrtf(rvar[(br * 4 + l + 1) * HID + n] + BN_EPS);
        g_wht[j] = to_tf32(Wh[j] * sc);
        return;
    }
    j -= N_WH;
    if (j < N_BI) {
        int n = j % HID, l = (j / HID) % 4, br = j / (4 * HID);
        int gi = (br * 4 + l) * HID + n;
        float sc = gamma[gi] * rsqrtf(rvar[gi] + BN_EPS);
        float b = (l == 0) ? b0[br * HID + n] : bh[((size_t)(br * 3) + (l - 1)) * HID + n];
        g_biasf[j] = (b - rmean[gi]) * sc + beta[gi];
    }
}

// ---------------- main fused MLP kernel (mma.sync tf32 + cp.async pipeline) ----------------
__global__ __launch_bounds__(256, 1)
void mlp_mma_kernel(const float* __restrict__ nf, const float* __restrict__ geo,
                    const int* __restrict__ eidx, const float* __restrict__ att,
                    float* __restrict__ out, int E, int G) {
    extern __shared__ float sm[];
    int* s_i = (int*)sm;
    int* s_j = s_i + 128;
    int* s_k = s_j + 128;
    int* s_e = s_k + 128;
    float* bias_s = sm + OFF_BIAS;
    float* Asm = sm + OFF_A;
    float* Bsm = sm + OFF_B;
    float* Hsm = sm + OFF_H;

    const int br = blockIdx.y;
    const int cnt = g_cnt[br];
    const int tstart = blockIdx.x * TILE;
    if (tstart >= cnt) return;
    const int ne = min(TILE, cnt - tstart);
    const int tid = threadIdx.x;
    const int warp = tid >> 5, lane = tid & 31;
    const int t4 = lane >> 2, tm4 = lane & 3;
    const int rbase = (warp & 1) * 64;        // M block of this warp
    const int nbase = (warp >> 1) * 64;       // N block of this warp
    const uint32_t bsm_u = smem_u32(Bsm);

    if (tid < 128) {
        int t = min(tid, ne - 1);             // pad tile with last valid edge
        int e = g_bucket[br * EMAX + tstart + t];
        s_e[tid] = e;
        s_i[tid] = eidx[e];
        s_j[tid] = eidx[E + e];
        s_k[tid] = eidx[2 * E + e];
    }
    __syncthreads();

    // precomputed per-thread staging coordinates
    const int brow = tid >> 6, bq = tid & 63;          // B: 4 rows of 4 threads each... (idx>>6, idx&63)
    const int arow0 = tid >> 2, aq = tid & 3;          // A: row pairs

    float acc[4][8][4];

    for (int l = 0; l < 4; l++) {
        const int nch = (l == 0) ? (KF0 / KC) : (HID / KC);
        const float* Wsrc = (l == 0) ? (g_w0t + (size_t)br * KF0 * HID)
                                     : (g_wht + ((size_t)(br * 3) + (l - 1)) * HID * HID);

        #pragma unroll
        for (int m = 0; m < 4; m++)
            #pragma unroll
            for (int n = 0; n < 8; n++)
                #pragma unroll
                for (int q = 0; q < 4; q++) acc[m][n][q] = 0.f;

        bias_s[tid] = g_biasf[((size_t)(br * 4) + l) * HID + tid];

        // ---- stage chunk 0 ----
        {   // B chunk 0 via cp.async (overlaps the A chunk-0 LDGs below)
            #pragma unroll
            for (int p = 0; p < 4; p++) {
                int idx = p * 256 + tid;
                int row = idx >> 6, q = idx & 63;
                cpa16(bsm_u + (row * BSTR + q * 4) * 4, Wsrc + row * HID + q * 4);
            }
            CPA_COMMIT();
        }
        if (l == 0) {   // A chunk 0 (features 0..15 of node i), rn-rounded
            #pragma unroll
            for (int p = 0; p < 2; p++) {
                int idx = p * 256 + tid;
                int row = idx >> 2, q = idx & 3;
                float4 v = *(const float4*)(nf + (size_t)s_i[row] * HID + q * 4);
                v.x = to_tf32(v.x); v.y = to_tf32(v.y);
                v.z = to_tf32(v.z); v.w = to_tf32(v.w);
                *(float4*)(Asm + row * ASTR + q * 4) = v;
            }
        }
        CPA_WAIT0();
        __syncthreads();

        for (int c = 0; c < nch; c++) {
            const int buf = c & 1;
            const bool have_next = (c + 1 < nch);
            const int nb = buf ^ 1;

            // ---- kick off async staging of chunk c+1 ----
            float4 pa4[2];                    // A prefetch regs (l0, feature chunks)
            float pg[8];                      // A prefetch regs (l0, geo chunk)
            bool geo_chunk = false;
            if (have_next) {
                {   // B via cp.async — latency hidden under MMA below
                    const float* src = Wsrc + (size_t)(c + 1) * KC * HID;
                    const uint32_t dst = bsm_u + nb * (KC * BSTR) * 4;
                    #pragma unroll
                    for (int p = 0; p < 4; p++) {
                        int idx = p * 256 + tid;
                        int row = idx >> 6, q = idx & 63;
                        cpa16(dst + (row * BSTR + q * 4) * 4, src + row * HID + q * 4);
                    }
                    CPA_COMMIT();
                }
                if (l == 0) {   // A gather prefetch into registers
                    const int cn = c + 1;
                    if (cn < 48) {
                        const int* sidx = (cn < 16) ? s_i : (cn < 32) ? s_j : s_k;
                        const int f0 = (cn & 15) * 16;
                        #pragma unroll
                        for (int p = 0; p < 2; p++) {
                            int idx = p * 256 + tid;
                            int row = idx >> 2, q = idx & 3;
                            pa4[p] = *(const float4*)(nf + (size_t)sidx[row] * HID + f0 + q * 4);
                        }
                    } else {
                        geo_chunk = true;
                        #pragma unroll
                        for (int p = 0; p < 8; p++) {
                            int idx = p * 256 + tid;
                            int row = idx >> 4, fi = idx & 15;
                            pg[p] = (fi < G) ? geo[(size_t)s_e[row] * G + fi] : 0.f;
                        }
                    }
                }
            }

            // ---- compute chunk c: 2 k-steps of 8 ----
            const float* Abase;
            int astr, koff;
            if (l == 0) { Abase = Asm + buf * (128 * ASTR); astr = ASTR; koff = 0; }
            else        { Abase = Hsm;                      astr = HSTR; koff = c * KC; }
            const float* Bbase = Bsm + buf * (KC * BSTR);

            #pragma unroll
            for (int s = 0; s < 2; s++) {
                float a[4][4];
                float b[8][2];
                #pragma unroll
                for (int m = 0; m < 4; m++) {
                    const float* ap = Abase + (rbase + m * 16 + t4) * astr + koff + s * 8 + tm4;
                    a[m][0] = ap[0];
                    a[m][1] = ap[8 * astr];
                    a[m][2] = ap[4];
                    a[m][3] = ap[8 * astr + 4];
                }
                #pragma unroll
                for (int n = 0; n < 8; n++) {
                    const float* bp = Bbase + (s * 8 + tm4) * BSTR + nbase + n * 8 + t4;
                    b[n][0] = bp[0];
                    b[n][1] = bp[4 * BSTR];
                }
                #pragma unroll
                for (int m = 0; m < 4; m++)
                    #pragma unroll
                    for (int n = 0; n < 8; n++)
                        mma8(acc[m][n], a[m], b[n]);
            }

            // ---- finish staging chunk c+1 ----
            if (have_next) {
                if (l == 0) {
                    float* dst = Asm + nb * (128 * ASTR);
                    if (!geo_chunk) {
                        #pragma unroll
                        for (int p = 0; p < 2; p++) {
                            int idx = p * 256 + tid;
                            int row = idx >> 2, q = idx & 3;
                            float4 v = pa4[p];
                            v.x = to_tf32(v.x); v.y = to_tf32(v.y);
                            v.z = to_tf32(v.z); v.w = to_tf32(v.w);
                            *(float4*)(dst + row * ASTR + q * 4) = v;
                        }
                    } else {
                        #pragma unroll
                        for (int p = 0; p < 8; p++) {
                            int idx = p * 256 + tid;
                            int row = idx >> 4, fi = idx & 15;
                            dst[row * ASTR + fi] = to_tf32(pg[p]);
                        }
                    }
                }
                CPA_WAIT0();
            }
            __syncthreads();
        }

        // ---- epilogue ----
        if (l < 3) {
            // bias + ReLU + tf32-rn -> Hsm (next layer's A)
            #pragma unroll
            for (int m = 0; m < 4; m++) {
                const int r0 = rbase + m * 16 + t4;
                #pragma unroll
                for (int n = 0; n < 8; n++) {
                    const int c0 = nbase + n * 8 + 2 * tm4;
                    const float b0v = bias_s[c0], b1v = bias_s[c0 + 1];
                    float2 v0, v1;
                    v0.x = to_tf32(fmaxf(acc[m][n][0] + b0v, 0.f));
                    v0.y = to_tf32(fmaxf(acc[m][n][1] + b1v, 0.f));
                    v1.x = to_tf32(fmaxf(acc[m][n][2] + b0v, 0.f));
                    v1.y = to_tf32(fmaxf(acc[m][n][3] + b1v, 0.f));
                    *(float2*)(Hsm + r0 * HSTR + c0) = v0;
                    *(float2*)(Hsm + (r0 + 8) * HSTR + c0) = v1;
                }
            }
            __syncthreads();
        } else {
            // bias + ReLU (leaky_relu identity on >=0), * att, scatter to out[i]
            const float attv = __ldg(att + br);
            #pragma unroll
            for (int m = 0; m < 4; m++) {
                const int r0 = rbase + m * 16 + t4;
                const int r1 = r0 + 8;
                float* o0 = (r0 < ne) ? (out + (size_t)s_i[r0] * HID) : 0;
                float* o1 = (r1 < ne) ? (out + (size_t)s_i[r1] * HID) : 0;
                #pragma unroll
                for (int n = 0; n < 8; n++) {
                    const int c0 = nbase + n * 8 + 2 * tm4;
                    const float b0v = bias_s[c0], b1v = bias_s[c0 + 1];
                    if (o0) red2(o0 + c0, fmaxf(acc[m][n][0] + b0v, 0.f) * attv,
                                          fmaxf(acc[m][n][1] + b1v, 0.f) * attv);
                    if (o1) red2(o1 + c0, fmaxf(acc[m][n][2] + b0v, 0.f) * attv,
                                          fmaxf(acc[m][n][3] + b1v, 0.f) * attv);
                }
            }
        }
    }
}

// ---------------- launch ----------------
extern "C" void kernel_launch(void* const* d_in, const int* in_sizes, int n_in,
                              void* d_out, int out_size) {
    const float* nf     = (const float*)d_in[0];
    const float* geo    = (const float*)d_in[1];
    const int*   eidx   = (const int*)d_in[2];
    const int*   edx_ij = (const int*)d_in[3];
    const int*   edx_jk = (const int*)d_in[4];
    const float* att    = (const float*)d_in[5];
    const float* W0     = (const float*)d_in[6];
    const float* b0     = (const float*)d_in[7];
    const float* Wh     = (const float*)d_in[8];
    const float* bh     = (const float*)d_in[9];
    const float* gamma  = (const float*)d_in[10];
    const float* beta   = (const float*)d_in[11];
    const float* rmean  = (const float*)d_in[12];
    const float* rvar   = (const float*)d_in[13];
    const int*   nei    = (const int*)d_in[14];

    int E = in_sizes[3];
    int G = in_sizes[1] / E;
    int din = 3 * HID + G;
    float* out = (float*)d_out;

    cudaMemsetAsync(out, 0, (size_t)out_size * sizeof(float), 0);
    reset_kernel<<<1, 32>>>();
    bucket_kernel<<<(E + 255) / 256, 256>>>(edx_ij, edx_jk, nei, E);

    int nprep = N_W0 + N_WH + N_BI;
    prep_all<<<(nprep + 255) / 256, 256>>>(W0, Wh, b0, bh, gamma, beta, rmean, rvar, din);

    cudaFuncSetAttribute(mlp_mma_kernel, cudaFuncAttributeMaxDynamicSharedMemorySize,
                         SMEM_BYTES);
    dim3 grid((E + TILE - 1) / TILE, 4);
    mlp_mma_kernel<<<grid, 256, SMEM_BYTES>>>(nf, geo, eidx, att, out, E, G);
}

// round 6
// speedup vs baseline: 7.5636x; 1.0603x over previous
#include <cuda_runtime.h>
#include <cstdint>

#define EMAX 131072
#define HID 256
#define TILE 64
#define KF0 784            // 781 padded to 49 chunks of 16
#define KC 16
#define BN_EPS 1e-5f

// smem strides (floats) — conflict-free mma fragment access
#define ASTR 20
#define BSTR 264
#define HSTR 260

// smem float offsets (TILE=64 layout)
#define OFF_BIAS 256                   // after 4*64 ints of edge indices
#define OFF_A    512                   // 2 * 64*20   = 2560
#define OFF_B    (OFF_A + 2560)        // 2 * 16*264  = 8448
#define OFF_H    (OFF_B + 8448)        // 64*260     = 16640
#define SMEM_BYTES ((OFF_H + 16640) * 4)   // 112640 B -> 2 CTAs/SM

static __device__ int   g_cnt[4];
static __device__ int   g_bucket[4 * EMAX];
static __device__ float g_w0t[4 * KF0 * HID];      // [br][kf][n], BN-folded, tf32-rn
static __device__ float g_wht[4 * 3 * HID * HID];  // [br][l][k][n], BN-folded, tf32-rn
static __device__ float g_biasf[4 * 4 * HID];      // [br][layer][n]

__device__ __forceinline__ float to_tf32(float x) {
    float r; asm("cvt.rn.tf32.f32 %0, %1;" : "=f"(r) : "f"(x)); return r;
}
__device__ __forceinline__ uint32_t smem_u32(const void* p) {
    uint32_t a;
    asm("{ .reg .u64 t; cvta.to.shared.u64 t, %1; cvt.u32.u64 %0, t; }" : "=r"(a) : "l"(p));
    return a;
}
__device__ __forceinline__ void cpa16(uint32_t dst, const void* src) {
    asm volatile("cp.async.cg.shared.global [%0], [%1], 16;" :: "r"(dst), "l"(src));
}
#define CPA_COMMIT() asm volatile("cp.async.commit_group;" ::: "memory")
#define CPA_WAIT0()  asm volatile("cp.async.wait_group 0;" ::: "memory")

__device__ __forceinline__ void mma8(float* d, const float* a, const float* b) {
    asm volatile(
        "mma.sync.aligned.m16n8k8.row.col.f32.tf32.tf32.f32 "
        "{%0,%1,%2,%3}, {%4,%5,%6,%7}, {%8,%9}, {%0,%1,%2,%3};"
        : "+f"(d[0]), "+f"(d[1]), "+f"(d[2]), "+f"(d[3])
        : "r"(__float_as_uint(a[0])), "r"(__float_as_uint(a[1])),
          "r"(__float_as_uint(a[2])), "r"(__float_as_uint(a[3])),
          "r"(__float_as_uint(b[0])), "r"(__float_as_uint(b[1])));
}

__device__ __forceinline__ void red2(float* p, float x, float y) {
    asm volatile("red.global.add.v2.f32 [%0], {%1,%2};" :: "l"(p), "f"(x), "f"(y) : "memory");
}

// ---------------- prep kernels ----------------
__global__ void reset_kernel() { if (threadIdx.x < 4) g_cnt[threadIdx.x] = 0; }

__global__ void bucket_kernel(const int* __restrict__ edx_ij, const int* __restrict__ edx_jk,
                              const int* __restrict__ nei_ptr, int E) {
    int e = blockIdx.x * blockDim.x + threadIdx.x;
    int lane = threadIdx.x & 31;
    bool valid = (e < E);
    int nei = nei_ptr[0];
    int br = 0;
    if (valid) {
        int mij = (edx_ij[e] < nei) ? 1 : 0;
        int mjk = (edx_jk[e] < nei) ? 1 : 0;
        br = ((mij ^ 1) << 1) | (mjk ^ 1);
    }
    #pragma unroll
    for (int b = 0; b < 4; b++) {
        unsigned m = __ballot_sync(0xffffffffu, valid && br == b);
        if (!m) continue;
        int leader = __ffs(m) - 1;
        int base = 0;
        if (lane == leader) base = atomicAdd(&g_cnt[b], __popc(m));
        base = __shfl_sync(0xffffffffu, base, leader);
        if (valid && br == b) {
            int rank = __popc(m & ((1u << lane) - 1u));
            g_bucket[b * EMAX + base + rank] = e;
        }
    }
}

#define N_W0 (4 * KF0 * HID)
#define N_WH (4 * 3 * HID * HID)
#define N_BI (4 * 4 * HID)
__global__ void prep_all(const float* __restrict__ W0, const float* __restrict__ Wh,
                         const float* __restrict__ b0, const float* __restrict__ bh,
                         const float* __restrict__ gamma, const float* __restrict__ beta,
                         const float* __restrict__ rmean, const float* __restrict__ rvar,
                         int din) {
    int idx = blockIdx.x * blockDim.x + threadIdx.x;
    if (idx < N_W0) {
        int n = idx % HID, kf = (idx / HID) % KF0, br = idx / (HID * KF0);
        float sc = gamma[(br * 4 + 0) * HID + n] * rsqrtf(rvar[(br * 4 + 0) * HID + n] + BN_EPS);
        float v = 0.f;
        if (kf < din) v = W0[((size_t)br * din + kf) * HID + n] * sc;
        g_w0t[idx] = to_tf32(v);
        return;
    }
    int j = idx - N_W0;
    if (j < N_WH) {
        int n = j % HID;
        int l = (j / (HID * HID)) % 3, br = j / (3 * HID * HID);
        float sc = gamma[(br * 4 + l + 1) * HID + n] *
                   rsqrtf(rvar[(br * 4 + l + 1) * HID + n] + BN_EPS);
        g_wht[j] = to_tf32(Wh[j] * sc);
        return;
    }
    j -= N_WH;
    if (j < N_BI) {
        int n = j % HID, l = (j / HID) % 4, br = j / (4 * HID);
        int gi = (br * 4 + l) * HID + n;
        float sc = gamma[gi] * rsqrtf(rvar[gi] + BN_EPS);
        float b = (l == 0) ? b0[br * HID + n] : bh[((size_t)(br * 3) + (l - 1)) * HID + n];
        g_biasf[j] = (b - rmean[gi]) * sc + beta[gi];
    }
}

// ---------------- main fused MLP kernel (mma.sync tf32, TILE=64, 2 CTA/SM) ----------------
__global__ __launch_bounds__(256, 2)
void mlp_mma_kernel(const float* __restrict__ nf, const float* __restrict__ geo,
                    const int* __restrict__ eidx, const float* __restrict__ att,
                    float* __restrict__ out, int E, int G) {
    extern __shared__ float sm[];
    int* s_i = (int*)sm;
    int* s_j = s_i + TILE;
    int* s_k = s_j + TILE;
    int* s_e = s_k + TILE;
    float* bias_s = sm + OFF_BIAS;
    float* Asm = sm + OFF_A;
    float* Bsm = sm + OFF_B;
    float* Hsm = sm + OFF_H;

    const int br = blockIdx.y;
    const int cnt = g_cnt[br];
    const int tstart = blockIdx.x * TILE;
    if (tstart >= cnt) return;
    const int ne = min(TILE, cnt - tstart);
    const int tid = threadIdx.x;
    const int warp = tid >> 5, lane = tid & 31;
    const int t4 = lane >> 2, tm4 = lane & 3;
    const int nbase = warp * 32;              // N block of this warp (M shared: 64 rows)
    const uint32_t bsm_u = smem_u32(Bsm);

    if (tid < 4 * TILE) {
        int which = tid >> 6, r = tid & (TILE - 1);
        int t = min(r, ne - 1);               // pad tile with last valid edge
        int e = g_bucket[br * EMAX + tstart + t];
        if (which == 0) { s_e[r] = e; s_i[r] = eidx[e]; }
        else if (which == 1) s_j[r] = eidx[E + e];
        else if (which == 2) s_k[r] = eidx[2 * E + e];
        else bias_s[r] = 0.f;                 // dummy lane use; bias loaded per layer below
    }
    __syncthreads();

    float acc[4][4][4];

    for (int l = 0; l < 4; l++) {
        const int nch = (l == 0) ? (KF0 / KC) : (HID / KC);
        const float* Wsrc = (l == 0) ? (g_w0t + (size_t)br * KF0 * HID)
                                     : (g_wht + ((size_t)(br * 3) + (l - 1)) * HID * HID);

        #pragma unroll
        for (int m = 0; m < 4; m++)
            #pragma unroll
            for (int n = 0; n < 4; n++)
                #pragma unroll
                for (int q = 0; q < 4; q++) acc[m][n][q] = 0.f;

        bias_s[tid] = g_biasf[((size_t)(br * 4) + l) * HID + tid];

        // ---- stage chunk 0 ----
        {   // B chunk 0 via cp.async
            #pragma unroll
            for (int p = 0; p < 4; p++) {
                int idx = p * 256 + tid;
                int row = idx >> 6, q = idx & 63;
                cpa16(bsm_u + (row * BSTR + q * 4) * 4, Wsrc + row * HID + q * 4);
            }
            CPA_COMMIT();
        }
        if (l == 0) {   // A chunk 0 (feats 0..15 of node i), rn-rounded
            int row = tid >> 2, q = tid & 3;
            float4 v = *(const float4*)(nf + (size_t)s_i[row] * HID + q * 4);
            v.x = to_tf32(v.x); v.y = to_tf32(v.y);
            v.z = to_tf32(v.z); v.w = to_tf32(v.w);
            *(float4*)(Asm + row * ASTR + q * 4) = v;
        }
        CPA_WAIT0();
        __syncthreads();

        for (int c = 0; c < nch; c++) {
            const int buf = c & 1;
            const bool have_next = (c + 1 < nch);
            const int nb = buf ^ 1;

            // ---- kick off async staging of chunk c+1 ----
            float4 pa4;                       // A prefetch regs (l0, feature chunks)
            float pg[4];                      // A prefetch regs (l0, geo chunk)
            bool geo_chunk = false;
            if (have_next) {
                {   // B via cp.async — hidden under MMA below
                    const float* src = Wsrc + (size_t)(c + 1) * KC * HID;
                    const uint32_t dst = bsm_u + nb * (KC * BSTR) * 4;
                    #pragma unroll
                    for (int p = 0; p < 4; p++) {
                        int idx = p * 256 + tid;
                        int row = idx >> 6, q = idx & 63;
                        cpa16(dst + (row * BSTR + q * 4) * 4, src + row * HID + q * 4);
                    }
                    CPA_COMMIT();
                }
                if (l == 0) {   // A gather prefetch into registers
                    const int cn = c + 1;
                    if (cn < 48) {
                        const int* sidx = (cn < 16) ? s_i : (cn < 32) ? s_j : s_k;
                        const int f0 = (cn & 15) * 16;
                        int row = tid >> 2, q = tid & 3;
                        pa4 = *(const float4*)(nf + (size_t)sidx[row] * HID + f0 + q * 4);
                    } else {
                        geo_chunk = true;
                        #pragma unroll
                        for (int p = 0; p < 4; p++) {
                            int idx = p * 256 + tid;
                            int row = idx >> 4, fi = idx & 15;
                            pg[p] = (fi < G) ? geo[(size_t)s_e[row] * G + fi] : 0.f;
                        }
                    }
                }
            }

            // ---- compute chunk c: 2 k-steps of 8 ----
            const float* Abase;
            int astr, koff;
            if (l == 0) { Abase = Asm + buf * (TILE * ASTR); astr = ASTR; koff = 0; }
            else        { Abase = Hsm;                       astr = HSTR; koff = c * KC; }
            const float* Bbase = Bsm + buf * (KC * BSTR);

            #pragma unroll
            for (int s = 0; s < 2; s++) {
                float a[4][4];
                float b[4][2];
                #pragma unroll
                for (int m = 0; m < 4; m++) {
                    const float* ap = Abase + (m * 16 + t4) * astr + koff + s * 8 + tm4;
                    a[m][0] = ap[0];
                    a[m][1] = ap[8 * astr];
                    a[m][2] = ap[4];
                    a[m][3] = ap[8 * astr + 4];
                }
                #pragma unroll
                for (int n = 0; n < 4; n++) {
                    const float* bp = Bbase + (s * 8 + tm4) * BSTR + nbase + n * 8 + t4;
                    b[n][0] = bp[0];
                    b[n][1] = bp[4 * BSTR];
                }
                #pragma unroll
                for (int m = 0; m < 4; m++)
                    #pragma unroll
                    for (int n = 0; n < 4; n++)
                        mma8(acc[m][n], a[m], b[n]);
            }

            // ---- finish staging chunk c+1 ----
            if (have_next) {
                if (l == 0) {
                    float* dst = Asm + nb * (TILE * ASTR);
                    if (!geo_chunk) {
                        int row = tid >> 2, q = tid & 3;
                        float4 v = pa4;
                        v.x = to_tf32(v.x); v.y = to_tf32(v.y);
                        v.z = to_tf32(v.z); v.w = to_tf32(v.w);
                        *(float4*)(dst + row * ASTR + q * 4) = v;
                    } else {
                        #pragma unroll
                        for (int p = 0; p < 4; p++) {
                            int idx = p * 256 + tid;
                            int row = idx >> 4, fi = idx & 15;
                            dst[row * ASTR + fi] = to_tf32(pg[p]);
                        }
                    }
                }
                CPA_WAIT0();
            }
            __syncthreads();
        }

        // ---- epilogue ----
        if (l < 3) {
            // bias + ReLU + tf32-rn -> Hsm (next layer's A)
            #pragma unroll
            for (int m = 0; m < 4; m++) {
                const int r0 = m * 16 + t4;
                #pragma unroll
                for (int n = 0; n < 4; n++) {
                    const int c0 = nbase + n * 8 + 2 * tm4;
                    const float b0v = bias_s[c0], b1v = bias_s[c0 + 1];
                    float2 v0, v1;
                    v0.x = to_tf32(fmaxf(acc[m][n][0] + b0v, 0.f));
                    v0.y = to_tf32(fmaxf(acc[m][n][1] + b1v, 0.f));
                    v1.x = to_tf32(fmaxf(acc[m][n][2] + b0v, 0.f));
                    v1.y = to_tf32(fmaxf(acc[m][n][3] + b1v, 0.f));
                    *(float2*)(Hsm + r0 * HSTR + c0) = v0;
                    *(float2*)(Hsm + (r0 + 8) * HSTR + c0) = v1;
                }
            }
            __syncthreads();
        } else {
            // bias + ReLU (leaky identity on >=0), * att, scatter to out[i]
            const float attv = __ldg(att + br);
            #pragma unroll
            for (int m = 0; m < 4; m++) {
                const int r0 = m * 16 + t4;
                const int r1 = r0 + 8;
                float* o0 = (r0 < ne) ? (out + (size_t)s_i[r0] * HID) : 0;
                float* o1 = (r1 < ne) ? (out + (size_t)s_i[r1] * HID) : 0;
                #pragma unroll
                for (int n = 0; n < 4; n++) {
                    const int c0 = nbase + n * 8 + 2 * tm4;
                    const float b0v = bias_s[c0], b1v = bias_s[c0 + 1];
                    if (o0) red2(o0 + c0, fmaxf(acc[m][n][0] + b0v, 0.f) * attv,
                                          fmaxf(acc[m][n][1] + b1v, 0.f) * attv);
                    if (o1) red2(o1 + c0, fmaxf(acc[m][n][2] + b0v, 0.f) * attv,
                                          fmaxf(acc[m][n][3] + b1v, 0.f) * attv);
                }
            }
        }
    }
}

// ---------------- launch ----------------
extern "C" void kernel_launch(void* const* d_in, const int* in_sizes, int n_in,
                              void* d_out, int out_size) {
    const float* nf     = (const float*)d_in[0];
    const float* geo    = (const float*)d_in[1];
    const int*   eidx   = (const int*)d_in[2];
    const int*   edx_ij = (const int*)d_in[3];
    const int*   edx_jk = (const int*)d_in[4];
    const float* att    = (const float*)d_in[5];
    const float* W0     = (const float*)d_in[6];
    const float* b0     = (const float*)d_in[7];
    const float* Wh     = (const float*)d_in[8];
    const float* bh     = (const float*)d_in[9];
    const float* gamma  = (const float*)d_in[10];
    const float* beta   = (const float*)d_in[11];
    const float* rmean  = (const float*)d_in[12];
    const float* rvar   = (const float*)d_in[13];
    const int*   nei    = (const int*)d_in[14];

    int E = in_sizes[3];
    int G = in_sizes[1] / E;
    int din = 3 * HID + G;
    float* out = (float*)d_out;

    cudaMemsetAsync(out, 0, (size_t)out_size * sizeof(float), 0);
    reset_kernel<<<1, 32>>>();
    bucket_kernel<<<(E + 255) / 256, 256>>>(edx_ij, edx_jk, nei, E);

    int nprep = N_W0 + N_WH + N_BI;
    prep_all<<<(nprep + 255) / 256, 256>>>(W0, Wh, b0, bh, gamma, beta, rmean, rvar, din);

    cudaFuncSetAttribute(mlp_mma_kernel, cudaFuncAttributeMaxDynamicSharedMemorySize,
                         SMEM_BYTES);
    dim3 grid((E + TILE - 1) / TILE, 4);
    mlp_mma_kernel<<<grid, 256, SMEM_BYTES>>>(nf, geo, eidx, att, out, E, G);
}

// round 7
// speedup vs baseline: 11.5328x; 1.5248x over previous
#include <cuda_runtime.h>
#include <cuda_fp16.h>
#include <cstdint>

#define EMAX 131072
#define HID 256
#define TILE 64
#define KF0 800            // 781 padded to 25 chunks of 32
#define KC 32
#define BN_EPS 1e-5f

// smem strides in HALVES — conflict-free fragment access
#define ASTRH 40
#define BSTRH 40
#define HSTRH 264

// smem byte offsets
#define OFFB_IDX  0          // 4 * 64 ints = 1024
#define OFFB_BIAS 1024       // 256 floats = 1024
#define OFFB_A    2048       // 2 * 64*40 halves  = 10240
#define OFFB_B    12288      // 2 * 256*40 halves = 40960
#define OFFB_H    53248      // 64*264 halves     = 33792
#define SMEM_BYTES 87040     // -> 2 CTAs/SM

static __device__ int    g_cnt[4];
static __device__ int    g_bucket[4 * EMAX];
static __device__ __half g_w0t[4 * HID * KF0];      // [br][n][kf] BN-folded fp16
static __device__ __half g_wht[4 * 3 * HID * HID];  // [br][l][n][k] BN-folded fp16
static __device__ float  g_biasf[4 * 4 * HID];      // [br][layer][n]

__device__ __forceinline__ uint32_t smem_u32(const void* p) {
    uint32_t a;
    asm("{ .reg .u64 t; cvta.to.shared.u64 t, %1; cvt.u32.u64 %0, t; }" : "=r"(a) : "l"(p));
    return a;
}
__device__ __forceinline__ void cpa16(uint32_t dst, const void* src) {
    asm volatile("cp.async.cg.shared.global [%0], [%1], 16;" :: "r"(dst), "l"(src));
}
#define CPA_COMMIT() asm volatile("cp.async.commit_group;" ::: "memory")
#define CPA_WAIT0()  asm volatile("cp.async.wait_group 0;" ::: "memory")

__device__ __forceinline__ void mma16(float* d, const uint32_t* a, const uint32_t* b) {
    asm volatile(
        "mma.sync.aligned.m16n8k16.row.col.f32.f16.f16.f32 "
        "{%0,%1,%2,%3}, {%4,%5,%6,%7}, {%8,%9}, {%0,%1,%2,%3};"
        : "+f"(d[0]), "+f"(d[1]), "+f"(d[2]), "+f"(d[3])
        : "r"(a[0]), "r"(a[1]), "r"(a[2]), "r"(a[3]), "r"(b[0]), "r"(b[1]));
}

__device__ __forceinline__ void red2(float* p, float x, float y) {
    asm volatile("red.global.add.v2.f32 [%0], {%1,%2};" :: "l"(p), "f"(x), "f"(y) : "memory");
}
__device__ __forceinline__ uint32_t h2u(float x, float y) {
    __half2 h = __floats2half2_rn(x, y);
    return *reinterpret_cast<uint32_t*>(&h);
}

// ---------------- prep kernels ----------------
__global__ void reset_kernel() { if (threadIdx.x < 4) g_cnt[threadIdx.x] = 0; }

__global__ void bucket_kernel(const int* __restrict__ edx_ij, const int* __restrict__ edx_jk,
                              const int* __restrict__ nei_ptr, int E) {
    int e = blockIdx.x * blockDim.x + threadIdx.x;
    int lane = threadIdx.x & 31;
    bool valid = (e < E);
    int nei = nei_ptr[0];
    int br = 0;
    if (valid) {
        int mij = (edx_ij[e] < nei) ? 1 : 0;
        int mjk = (edx_jk[e] < nei) ? 1 : 0;
        br = ((mij ^ 1) << 1) | (mjk ^ 1);
    }
    #pragma unroll
    for (int b = 0; b < 4; b++) {
        unsigned m = __ballot_sync(0xffffffffu, valid && br == b);
        if (!m) continue;
        int leader = __ffs(m) - 1;
        int base = 0;
        if (lane == leader) base = atomicAdd(&g_cnt[b], __popc(m));
        base = __shfl_sync(0xffffffffu, base, leader);
        if (valid && br == b) {
            int rank = __popc(m & ((1u << lane) - 1u));
            g_bucket[b * EMAX + base + rank] = e;
        }
    }
}

#define N_W0 (4 * HID * KF0)
#define N_WH (4 * 3 * HID * HID)
#define N_BI (4 * 4 * HID)
// W folded+transposed to [n][k] fp16; bias folded fp32.
__global__ void prep_all(const float* __restrict__ W0, const float* __restrict__ Wh,
                         const float* __restrict__ b0, const float* __restrict__ bh,
                         const float* __restrict__ gamma, const float* __restrict__ beta,
                         const float* __restrict__ rmean, const float* __restrict__ rvar,
                         int din) {
    int idx = blockIdx.x * blockDim.x + threadIdx.x;
    if (idx < N_W0) {
        int kf = idx % KF0, n = (idx / KF0) % HID, br = idx / (KF0 * HID);
        float sc = gamma[(br * 4 + 0) * HID + n] * rsqrtf(rvar[(br * 4 + 0) * HID + n] + BN_EPS);
        float v = 0.f;
        if (kf < din) v = W0[((size_t)br * din + kf) * HID + n] * sc;
        g_w0t[idx] = __float2half_rn(v);
        return;
    }
    int j = idx - N_W0;
    if (j < N_WH) {
        int k = j % HID, n = (j / HID) % HID;
        int l = (j / (HID * HID)) % 3, br = j / (3 * HID * HID);
        float sc = gamma[(br * 4 + l + 1) * HID + n] *
                   rsqrtf(rvar[(br * 4 + l + 1) * HID + n] + BN_EPS);
        float v = Wh[(((size_t)(br * 3 + l)) * HID + k) * HID + n] * sc;
        g_wht[j] = __float2half_rn(v);
        return;
    }
    j -= N_WH;
    if (j < N_BI) {
        int n = j % HID, l = (j / HID) % 4, br = j / (4 * HID);
        int gi = (br * 4 + l) * HID + n;
        float sc = gamma[gi] * rsqrtf(rvar[gi] + BN_EPS);
        float b = (l == 0) ? b0[br * HID + n] : bh[((size_t)(br * 3) + (l - 1)) * HID + n];
        g_biasf[j] = (b - rmean[gi]) * sc + beta[gi];
    }
}

// ---------------- main fused MLP kernel (fp16 mma, KC=32, 2 CTA/SM) ----------------
__global__ __launch_bounds__(256, 2)
void mlp_mma_kernel(const float* __restrict__ nf, const float* __restrict__ geo,
                    const int* __restrict__ eidx, const float* __restrict__ att,
                    float* __restrict__ out, int E, int G) {
    extern __shared__ char smc[];
    int* s_i = (int*)(smc + OFFB_IDX);
    int* s_j = s_i + TILE;
    int* s_k = s_j + TILE;
    int* s_e = s_k + TILE;
    float* bias_s = (float*)(smc + OFFB_BIAS);
    __half* Asm = (__half*)(smc + OFFB_A);
    __half* Bsm = (__half*)(smc + OFFB_B);
    __half* Hsm = (__half*)(smc + OFFB_H);

    const int br = blockIdx.y;
    const int cnt = g_cnt[br];
    const int tstart = blockIdx.x * TILE;
    if (tstart >= cnt) return;
    const int ne = min(TILE, cnt - tstart);
    const int tid = threadIdx.x;
    const int warp = tid >> 5, lane = tid & 31;
    const int t4 = lane >> 2, tm4 = lane & 3;
    const int nbase = warp * 32;              // N block of this warp (M shared: 64 rows)
    const uint32_t bsm_u = smem_u32(Bsm);

    if (tid < 3 * TILE) {
        int which = tid >> 6, r = tid & (TILE - 1);
        int t = min(r, ne - 1);               // pad tile with last valid edge
        int e = g_bucket[br * EMAX + tstart + t];
        if (which == 0) { s_e[r] = e; s_i[r] = eidx[e]; }
        else if (which == 1) s_j[r] = eidx[E + e];
        else s_k[r] = eidx[2 * E + e];
    }
    __syncthreads();

    const int arow = tid >> 2, aq = tid & 3;  // A staging coords
    float acc[4][4][4];

    for (int l = 0; l < 4; l++) {
        const int nch = (l == 0) ? (KF0 / KC) : (HID / KC);   // 25 or 8
        const __half* Wsrc = (l == 0) ? (g_w0t + (size_t)br * HID * KF0)
                                      : (g_wht + ((size_t)(br * 3) + (l - 1)) * HID * HID);
        const int wstr = (l == 0) ? KF0 : HID;

        #pragma unroll
        for (int m = 0; m < 4; m++)
            #pragma unroll
            for (int n = 0; n < 4; n++)
                #pragma unroll
                for (int q = 0; q < 4; q++) acc[m][n][q] = 0.f;

        bias_s[tid] = g_biasf[((size_t)(br * 4) + l) * HID + tid];

        // ---- stage chunk 0 ----
        {   // B chunk 0 via cp.async: 256 n-rows x 32 k-halves (64B) each
            #pragma unroll
            for (int p = 0; p < 4; p++) {
                int idx = p * 256 + tid;
                int row = idx >> 2, sub = idx & 3;
                cpa16(bsm_u + row * (BSTRH * 2) + sub * 16,
                      Wsrc + (size_t)row * wstr + sub * 8);
            }
            CPA_COMMIT();
        }
        if (l == 0) {   // A chunk 0: node-i feats 0..31, rn-rounded to fp16
            const float* src = nf + (size_t)s_i[arow] * HID + aq * 8;
            float4 v0 = *(const float4*)(src);
            float4 v1 = *(const float4*)(src + 4);
            uint4 u = { h2u(v0.x, v0.y), h2u(v0.z, v0.w), h2u(v1.x, v1.y), h2u(v1.z, v1.w) };
            *(uint4*)(Asm + arow * ASTRH + aq * 8) = u;
        }
        CPA_WAIT0();
        __syncthreads();

        for (int c = 0; c < nch; c++) {
            const int buf = c & 1;
            const bool have_next = (c + 1 < nch);
            const int nb = buf ^ 1;

            // ---- kick off async staging of chunk c+1 ----
            float4 pa0, pa1;                  // A prefetch regs (l0, feature chunks)
            float pg[8];                      // A prefetch regs (l0, geo chunk)
            bool geo_chunk = false;
            if (have_next) {
                {   // B via cp.async — latency hidden under MMA below
                    const __half* src = Wsrc + (size_t)(c + 1) * KC;
                    const uint32_t dst = bsm_u + nb * (256 * BSTRH * 2);
                    #pragma unroll
                    for (int p = 0; p < 4; p++) {
                        int idx = p * 256 + tid;
                        int row = idx >> 2, sub = idx & 3;
                        cpa16(dst + row * (BSTRH * 2) + sub * 16,
                              src + (size_t)row * wstr + sub * 8);
                    }
                    CPA_COMMIT();
                }
                if (l == 0) {   // A gather prefetch into registers
                    const int cn = c + 1;
                    if (cn < 24) {
                        const int* sidx = (cn < 8) ? s_i : (cn < 16) ? s_j : s_k;
                        const float* src = nf + (size_t)sidx[arow] * HID + (cn & 7) * 32 + aq * 8;
                        pa0 = *(const float4*)(src);
                        pa1 = *(const float4*)(src + 4);
                    } else {
                        geo_chunk = true;
                        #pragma unroll
                        for (int p = 0; p < 8; p++) {
                            int idx = p * 256 + tid;
                            int row = idx >> 5, fi = idx & 31;
                            pg[p] = (fi < G) ? geo[(size_t)s_e[row] * G + fi] : 0.f;
                        }
                    }
                }
            }

            // ---- compute chunk c: 2 k-steps of 16 ----
            const __half* Abase;
            int astr, koff;
            if (l == 0) { Abase = Asm + buf * (TILE * ASTRH); astr = ASTRH; koff = 0; }
            else        { Abase = Hsm;                        astr = HSTRH; koff = c * KC; }
            const __half* Bbase = Bsm + buf * (256 * BSTRH);

            #pragma unroll
            for (int s = 0; s < 2; s++) {
                uint32_t a[4][4];
                uint32_t b[4][2];
                #pragma unroll
                for (int m = 0; m < 4; m++) {
                    const __half* ap = Abase + (m * 16 + t4) * astr + koff + s * 16 + 2 * tm4;
                    a[m][0] = *(const uint32_t*)(ap);
                    a[m][1] = *(const uint32_t*)(ap + 8 * astr);
                    a[m][2] = *(const uint32_t*)(ap + 8);
                    a[m][3] = *(const uint32_t*)(ap + 8 * astr + 8);
                }
                #pragma unroll
                for (int n = 0; n < 4; n++) {
                    const __half* bp = Bbase + (nbase + n * 8 + t4) * BSTRH + s * 16 + 2 * tm4;
                    b[n][0] = *(const uint32_t*)(bp);
                    b[n][1] = *(const uint32_t*)(bp + 8);
                }
                #pragma unroll
                for (int m = 0; m < 4; m++)
                    #pragma unroll
                    for (int n = 0; n < 4; n++)
                        mma16(acc[m][n], a[m], b[n]);
            }

            // ---- finish staging chunk c+1 ----
            if (have_next) {
                if (l == 0) {
                    __half* dst = Asm + nb * (TILE * ASTRH);
                    if (!geo_chunk) {
                        uint4 u = { h2u(pa0.x, pa0.y), h2u(pa0.z, pa0.w),
                                    h2u(pa1.x, pa1.y), h2u(pa1.z, pa1.w) };
                        *(uint4*)(dst + arow * ASTRH + aq * 8) = u;
                    } else {
                        #pragma unroll
                        for (int p = 0; p < 8; p++) {
                            int idx = p * 256 + tid;
                            int row = idx >> 5, fi = idx & 31;
                            dst[row * ASTRH + fi] = __float2half_rn(pg[p]);
                        }
                    }
                }
                CPA_WAIT0();
            }
            __syncthreads();
        }

        // ---- epilogue ----
        if (l < 3) {
            // bias + ReLU -> fp16 rn -> Hsm (next layer's A)
            #pragma unroll
            for (int m = 0; m < 4; m++) {
                const int r0 = m * 16 + t4;
                #pragma unroll
                for (int n = 0; n < 4; n++) {
                    const int c0 = nbase + n * 8 + 2 * tm4;
                    const float b0v = bias_s[c0], b1v = bias_s[c0 + 1];
                    *(uint32_t*)(Hsm + r0 * HSTRH + c0) =
                        h2u(fmaxf(acc[m][n][0] + b0v, 0.f), fmaxf(acc[m][n][1] + b1v, 0.f));
                    *(uint32_t*)(Hsm + (r0 + 8) * HSTRH + c0) =
                        h2u(fmaxf(acc[m][n][2] + b0v, 0.f), fmaxf(acc[m][n][3] + b1v, 0.f));
                }
            }
            __syncthreads();
        } else {
            // bias + ReLU (leaky identity on >=0), * att, fp32 scatter to out[i]
            const float attv = __ldg(att + br);
            #pragma unroll
            for (int m = 0; m < 4; m++) {
                const int r0 = m * 16 + t4;
                const int r1 = r0 + 8;
                float* o0 = (r0 < ne) ? (out + (size_t)s_i[r0] * HID) : 0;
                float* o1 = (r1 < ne) ? (out + (size_t)s_i[r1] * HID) : 0;
                #pragma unroll
                for (int n = 0; n < 4; n++) {
                    const int c0 = nbase + n * 8 + 2 * tm4;
                    const float b0v = bias_s[c0], b1v = bias_s[c0 + 1];
                    if (o0) red2(o0 + c0, fmaxf(acc[m][n][0] + b0v, 0.f) * attv,
                                          fmaxf(acc[m][n][1] + b1v, 0.f) * attv);
                    if (o1) red2(o1 + c0, fmaxf(acc[m][n][2] + b0v, 0.f) * attv,
                                          fmaxf(acc[m][n][3] + b1v, 0.f) * attv);
                }
            }
        }
    }
}

// ---------------- launch ----------------
extern "C" void kernel_launch(void* const* d_in, const int* in_sizes, int n_in,
                              void* d_out, int out_size) {
    const float* nf     = (const float*)d_in[0];
    const float* geo    = (const float*)d_in[1];
    const int*   eidx   = (const int*)d_in[2];
    const int*   edx_ij = (const int*)d_in[3];
    const int*   edx_jk = (const int*)d_in[4];
    const float* att    = (const float*)d_in[5];
    const float* W0     = (const float*)d_in[6];
    const float* b0     = (const float*)d_in[7];
    const float* Wh     = (const float*)d_in[8];
    const float* bh     = (const float*)d_in[9];
    const float* gamma  = (const float*)d_in[10];
    const float* beta   = (const float*)d_in[11];
    const float* rmean  = (const float*)d_in[12];
    const float* rvar   = (const float*)d_in[13];
    const int*   nei    = (const int*)d_in[14];

    int E = in_sizes[3];
    int G = in_sizes[1] / E;
    int din = 3 * HID + G;
    float* out = (float*)d_out;

    cudaMemsetAsync(out, 0, (size_t)out_size * sizeof(float), 0);
    reset_kernel<<<1, 32>>>();
    bucket_kernel<<<(E + 255) / 256, 256>>>(edx_ij, edx_jk, nei, E);

    int nprep = N_W0 + N_WH + N_BI;
    prep_all<<<(nprep + 255) / 256, 256>>>(W0, Wh, b0, bh, gamma, beta, rmean, rvar, din);

    cudaFuncSetAttribute(mlp_mma_kernel, cudaFuncAttributeMaxDynamicSharedMemorySize,
                         SMEM_BYTES);
    dim3 grid((E + TILE - 1) / TILE, 4);
    mlp_mma_kernel<<<grid, 256, SMEM_BYTES>>>(nf, geo, eidx, att, out, E, G);
}